// round 13
// baseline (speedup 1.0000x reference)
#include <cuda_runtime.h>
#include <math.h>

#define BB 128
#define SS 512
#define EE 256
#define HH 256
#define G4 1024
#define NT 20
#define M_TOT (BB*SS)          // 65536
#define NBLK 64                // blocks per direction in lstm kernel
#define DPB 4                  // hidden dims per block

typedef unsigned long long ull;

// -------- device scratch (static: no allocations allowed) --------
__device__ float g_xp[2 * M_TOT * G4];     // [dir][m][1024]  (536 MB)
__device__ float g_hout[2 * M_TOT * HH];   // [dir][b*S+t][H]
__device__ float g_hcur[2 * 2 * HH * BB];  // [dir][parity][hd][b]
__device__ float g_emis[M_TOT * NT];       // [b*S+s][T]
__device__ unsigned g_bar_cnt[2];
__device__ unsigned g_bar_flag[2];

// smem: h 256*128, w_dup 256*32, g 16*128, c 4*128
#define LSTM_SMEM ((256*128 + 256*32 + 16*128 + 4*128) * 4)

// -------- packed f32x2 helpers (FFMA2 path, exact fp32) --------
__device__ __forceinline__ ull pk2(float lo, float hi) {
    ull r; asm("mov.b64 %0, {%1, %2};" : "=l"(r) : "f"(lo), "f"(hi)); return r;
}
__device__ __forceinline__ void upk2(ull v, float& lo, float& hi) {
    asm("mov.b64 {%0, %1}, %2;" : "=f"(lo), "=f"(hi) : "l"(v));
}
__device__ __forceinline__ void fma2(ull& d, ull a, ull b) {
    asm("fma.rn.f32x2 %0, %1, %2, %0;" : "+l"(d) : "l"(a), "l"(b));
}
__device__ __forceinline__ void add2(ull& d, ull a) {
    asm("add.rn.f32x2 %0, %0, %1;" : "+l"(d) : "l"(a));
}
__device__ __forceinline__ void cp16(unsigned dst, const void* src) {
    asm volatile("cp.async.cg.shared.global [%0], [%1], 16;" :: "r"(dst), "l"(src));
}
#define CP_COMMIT() asm volatile("cp.async.commit_group;")

// ---------------- init: reset barriers + zero h state ----------------
__global__ void init_kernel() {
    int idx = blockIdx.x * blockDim.x + threadIdx.x;
    int stride = gridDim.x * blockDim.x;
    for (int i = idx; i < 2 * 2 * HH * BB; i += stride) g_hcur[i] = 0.f;
    if (idx == 0) {
        g_bar_cnt[0] = 0; g_bar_cnt[1] = 0;
        g_bar_flag[0] = 0; g_bar_flag[1] = 0;
    }
}

// ---------------- input projection: xp = emb[xs] @ W_ih^T + b ----------------
// 64x64 tile, K=256 in 16-wide panels, 256 threads, 4x4 per thread (FFMA2 over row pairs),
// register double-buffered panel prefetch.
__global__ void input_proj_kernel(const int* __restrict__ xs,
                                  const float* __restrict__ emb,
                                  const float* __restrict__ W_f,
                                  const float* __restrict__ b_f,
                                  const float* __restrict__ W_r,
                                  const float* __restrict__ b_r)
{
    const int dir = blockIdx.z;
    const float* W    = dir ? W_r : W_f;
    const float* bias = dir ? b_r : b_f;
    const int m0 = blockIdx.x * 64;
    const int n0 = blockIdx.y * 64;

    __shared__ float As[16][68];    // [k][row]
    __shared__ float Bs[16][140];   // [k][2*col] duplicated pairs

    const int tid = threadIdx.x;
    const int lr = tid >> 2;          // 0..63 row within tile
    const int lk = (tid & 3) * 4;     // k sub-offset 0,4,8,12

    const int tok = xs[m0 + lr];
    const float* arow = emb + (size_t)tok * EE;
    const float* brow = W + (size_t)(n0 + lr) * EE;

    const int ty = tid >> 4;          // 0..15 -> rows ty*4..+3
    const int tx = tid & 15;          // 0..15 -> cols tx*4..+3

    ull acc2[2][4];                   // [row-pair][col]
    #pragma unroll
    for (int i = 0; i < 2; i++)
        #pragma unroll
        for (int j = 0; j < 4; j++) acc2[i][j] = 0ull;

    float4 av = *(const float4*)(arow + lk);
    float4 bv = *(const float4*)(brow + lk);

    #pragma unroll 1
    for (int p = 0; p < 16; p++) {
        __syncthreads();
        As[lk+0][lr] = av.x; As[lk+1][lr] = av.y; As[lk+2][lr] = av.z; As[lk+3][lr] = av.w;
        Bs[lk+0][2*lr] = bv.x; Bs[lk+0][2*lr+1] = bv.x;
        Bs[lk+1][2*lr] = bv.y; Bs[lk+1][2*lr+1] = bv.y;
        Bs[lk+2][2*lr] = bv.z; Bs[lk+2][2*lr+1] = bv.z;
        Bs[lk+3][2*lr] = bv.w; Bs[lk+3][2*lr+1] = bv.w;
        __syncthreads();
        if (p < 15) {
            av = *(const float4*)(arow + (p + 1) * 16 + lk);
            bv = *(const float4*)(brow + (p + 1) * 16 + lk);
        }
        #pragma unroll
        for (int k = 0; k < 16; k++) {
            ulonglong2 a  = *(const ulonglong2*)(&As[k][ty * 4]);     // rows (0,1),(2,3)
            ulonglong2 w0 = *(const ulonglong2*)(&Bs[k][tx * 8]);     // (c0,c0),(c1,c1)
            ulonglong2 w1 = *(const ulonglong2*)(&Bs[k][tx * 8 + 4]); // (c2,c2),(c3,c3)
            fma2(acc2[0][0], a.x, w0.x); fma2(acc2[0][1], a.x, w0.y);
            fma2(acc2[0][2], a.x, w1.x); fma2(acc2[0][3], a.x, w1.y);
            fma2(acc2[1][0], a.y, w0.x); fma2(acc2[1][1], a.y, w0.y);
            fma2(acc2[1][2], a.y, w1.x); fma2(acc2[1][3], a.y, w1.y);
        }
    }

    float acc[4][4];
    #pragma unroll
    for (int ip = 0; ip < 2; ip++)
        #pragma unroll
        for (int j = 0; j < 4; j++)
            upk2(acc2[ip][j], acc[2*ip][j], acc[2*ip+1][j]);

    const size_t base = (size_t)dir * M_TOT * G4;
    const int n = n0 + tx * 4;
    float4 bv4 = *(const float4*)(bias + n);
    #pragma unroll
    for (int i = 0; i < 4; i++) {
        int m = m0 + ty * 4 + i;
        float4 o;
        o.x = acc[i][0] + bv4.x; o.y = acc[i][1] + bv4.y;
        o.z = acc[i][2] + bv4.z; o.w = acc[i][3] + bv4.w;
        *(float4*)(g_xp + base + (size_t)m * G4 + n) = o;
    }
}

// ---------------- persistent bidirectional LSTM recurrence ----------------
// 128 blocks: [0,64) forward, [64,128) reverse. Block owns 4 hidden dims (16 gate cols).
// FFMA2 GEMM + cp.async chunked h staging overlapped with compute.
__global__ void __launch_bounds__(256, 1) lstm_kernel(const float* __restrict__ W_f,
                                                      const float* __restrict__ W_r)
{
    extern __shared__ float sm[];
    float* h_s = sm;                       // [k=256][b=128]
    float* w_s = h_s + 256 * 128;          // [k=256][2c=32] duplicated pairs
    float* g_s = w_s + 256 * 32;           // [c=16][b=128]
    float* c_s = g_s + 16 * 128;           // [d=4][b=128]

    const int tid = threadIdx.x;
    const int dir = blockIdx.x >> 6;
    const int blk = blockIdx.x & 63;
    const int d0  = blk * DPB;
    const float* W = dir ? W_r : W_f;

    // load W slice transposed + duplicated: w_s[k][2c],[2c+1] = W[q*256+d0+d][k]
    {
        const int c  = tid >> 4;               // 0..15
        const int q  = c >> 2, dd = c & 3;
        const int grow = q * 256 + d0 + dd;
        const int kc = (tid & 15) * 16;
        const float* wp = W + (size_t)grow * 256 + kc;
        #pragma unroll
        for (int kk = 0; kk < 16; kk++) {
            float v = wp[kk];
            w_s[(kc + kk) * 32 + 2 * c]     = v;
            w_s[(kc + kk) * 32 + 2 * c + 1] = v;
        }
    }
    for (int i = tid; i < DPB * BB; i += 256) c_s[i] = 0.f;
    __syncthreads();

    const int bg = tid >> 3;             // 0..31  -> batches bg*4..+3
    const int cg = tid & 7;              // 0..7   -> cols 2cg, 2cg+1
    const int b0 = bg * 4;
    const int c0 = cg * 2, c1 = cg * 2 + 1;
    const int grow0 = (c0 >> 2) * 256 + d0 + (c0 & 3);
    const int grow1 = (c1 >> 2) * 256 + d0 + (c1 & 3);

    const float* xp_base   = g_xp   + (size_t)dir * M_TOT * G4;
    float*       hout_base = g_hout + (size_t)dir * M_TOT * HH;
    const unsigned h_addr = (unsigned)__cvta_generic_to_shared(h_s);

    for (int ti = 0; ti < SS; ti++) {
        const int t = dir ? (SS - 1 - ti) : ti;
        const int par = ti & 1;
        const float* hr = g_hcur + (dir * 2 + par) * (HH * BB);
        float*       hw = g_hcur + (dir * 2 + (par ^ 1)) * (HH * BB);

        // issue cp.async for all 4 k-chunks (each 64 rows = 32KB); L2-coherent path
        {
            const float4* src = (const float4*)hr;
            #pragma unroll
            for (int ch = 0; ch < 4; ch++) {
                #pragma unroll
                for (int i = 0; i < 8; i++) {
                    int idx = ch * 2048 + i * 256 + tid;
                    cp16(h_addr + idx * 16, src + idx);
                }
                CP_COMMIT();
            }
        }

        // prefetch this step's xp contributions (8 scalars), pack to f32x2
        ull xq00, xq10, xq01, xq11;
        {
            float xpv[4][2];
            #pragma unroll
            for (int i = 0; i < 4; i++) {
                const float* xr = xp_base + ((size_t)(b0 + i) * SS + t) * G4;
                xpv[i][0] = __ldg(xr + grow0);
                xpv[i][1] = __ldg(xr + grow1);
            }
            xq00 = pk2(xpv[0][0], xpv[1][0]); xq10 = pk2(xpv[2][0], xpv[3][0]);
            xq01 = pk2(xpv[0][1], xpv[1][1]); xq11 = pk2(xpv[2][1], xpv[3][1]);
        }

        ull a00 = 0ull, a10 = 0ull, a01 = 0ull, a11 = 0ull;

        #pragma unroll
        for (int ch = 0; ch < 4; ch++) {
            if (ch == 0)      asm volatile("cp.async.wait_group 3;");
            else if (ch == 1) asm volatile("cp.async.wait_group 2;");
            else if (ch == 2) asm volatile("cp.async.wait_group 1;");
            else              asm volatile("cp.async.wait_group 0;");
            __syncthreads();
            #pragma unroll 8
            for (int k = ch * 64; k < ch * 64 + 64; k++) {
                ulonglong2 hv = *(const ulonglong2*)(h_s + k * BB + b0);      // (b0,b0+1),(b0+2,b0+3)
                ulonglong2 wv = *(const ulonglong2*)(w_s + k * 32 + cg * 4);  // (w0,w0),(w1,w1)
                fma2(a00, hv.x, wv.x); fma2(a10, hv.y, wv.x);
                fma2(a01, hv.x, wv.y); fma2(a11, hv.y, wv.y);
            }
        }

        add2(a00, xq00); add2(a10, xq10);
        add2(a01, xq01); add2(a11, xq11);
        {
            ulonglong2 s0; s0.x = a00; s0.y = a10;
            ulonglong2 s1; s1.x = a01; s1.y = a11;
            *(ulonglong2*)(g_s + c0 * BB + b0) = s0;
            *(ulonglong2*)(g_s + c1 * BB + b0) = s1;
        }
        __syncthreads();

        // gate math: 512 (d,b) pairs, 2 per thread
        #pragma unroll
        for (int r = 0; r < 2; r++) {
            const int idx = tid + r * 256;
            const int d = idx >> 7, b = idx & 127;
            const float gi = g_s[(0 * 4 + d) * BB + b];
            const float gf = g_s[(1 * 4 + d) * BB + b];
            const float gg = g_s[(2 * 4 + d) * BB + b];
            const float go = g_s[(3 * 4 + d) * BB + b];
            const float cp = c_s[d * BB + b];
            const float si = 1.f / (1.f + expf(-gi));
            const float sf = 1.f / (1.f + expf(-gf));
            const float so = 1.f / (1.f + expf(-go));
            const float cn = sf * cp + si * tanhf(gg);
            const float hv = so * tanhf(cn);
            c_s[d * BB + b] = cn;
            __stcg(hw + (d0 + d) * BB + b, hv);
            hout_base[((size_t)b * SS + t) * HH + d0 + d] = hv;
        }

        // grid barrier for this direction (monotonic count + flag; ld.cg polling)
        __syncthreads();
        if (tid == 0) {
            __threadfence();
            const unsigned target = (unsigned)(NBLK * (ti + 1));
            const unsigned a = atomicAdd(&g_bar_cnt[dir], 1u);
            if (a == target - 1) {
                atomicExch(&g_bar_flag[dir], (unsigned)(ti + 1));
            } else {
                const unsigned* fp = &g_bar_flag[dir];
                unsigned f;
                do {
                    asm volatile("ld.global.cg.u32 %0, [%1];" : "=r"(f) : "l"(fp));
                    if (f >= (unsigned)(ti + 1)) break;
                    __nanosleep(32);
                } while (true);
            }
        }
        __syncthreads();
    }
}

// ---------------- emissions: concat(h_f,h_r) @ fc_W^T + fc_b ----------------
__global__ void emis_kernel(const float* __restrict__ fcW, const float* __restrict__ fcb)
{
    __shared__ float w_sh[NT * 2 * HH];   // 40 KB
    __shared__ float b_sh[NT];
    const int tid = threadIdx.x;
    for (int i = tid; i < NT * 2 * HH; i += 256) w_sh[i] = fcW[i];
    if (tid < NT) b_sh[tid] = fcb[tid];
    __syncthreads();

    const int warp = tid >> 5, lane = tid & 31;
    const int pos = blockIdx.x * 8 + warp;  // 0..65535
    const float* hf = g_hout + (size_t)pos * HH;
    const float* hr = g_hout + (size_t)M_TOT * HH + (size_t)pos * HH;

    ulonglong2 Fa = *(const ulonglong2*)(hf + lane * 8);
    ulonglong2 Fb = *(const ulonglong2*)(hf + lane * 8 + 4);
    ulonglong2 Ra = *(const ulonglong2*)(hr + lane * 8);
    ulonglong2 Rb = *(const ulonglong2*)(hr + lane * 8 + 4);

    for (int tg = 0; tg < NT; tg++) {
        const float* w = w_sh + tg * 2 * HH;
        ulonglong2 Wa = *(const ulonglong2*)(w + lane * 8);
        ulonglong2 Wb = *(const ulonglong2*)(w + lane * 8 + 4);
        ulonglong2 Va = *(const ulonglong2*)(w + HH + lane * 8);
        ulonglong2 Vb = *(const ulonglong2*)(w + HH + lane * 8 + 4);
        ull acc = 0ull;
        fma2(acc, Fa.x, Wa.x); fma2(acc, Fa.y, Wa.y);
        fma2(acc, Fb.x, Wb.x); fma2(acc, Fb.y, Wb.y);
        fma2(acc, Ra.x, Va.x); fma2(acc, Ra.y, Va.y);
        fma2(acc, Rb.x, Vb.x); fma2(acc, Rb.y, Vb.y);
        float lo, hi; upk2(acc, lo, hi);
        float s = lo + hi;
        #pragma unroll
        for (int off = 16; off; off >>= 1) s += __shfl_xor_sync(0xffffffffu, s, off);
        if (lane == 0) g_emis[(size_t)pos * NT + tg] = s + b_sh[tg];
    }
}

// ---------------- Viterbi: one block (1 warp) per batch item ----------------
__global__ void viterbi_kernel(const int* __restrict__ xs,
                               const float* __restrict__ trans,
                               const float* __restrict__ start_t,
                               const float* __restrict__ end_t,
                               float* __restrict__ out,
                               int write_scores, int write_tags, int tag_off)
{
    __shared__ float tr[NT * NT];
    __shared__ float sc[NT];
    __shared__ unsigned char bp[SS * NT];

    const int b = blockIdx.x, tid = threadIdx.x;
    for (int i = tid; i < NT * NT; i += 32) tr[i] = trans[i];
    if (tid < NT) sc[tid] = start_t[tid] + g_emis[(size_t)b * SS * NT + tid];
    __syncwarp();

    for (int s = 1; s < SS; s++) {
        float ns = 0.f; int nb = 0;
        if (tid < NT) {
            float best = -1e30f; int bi = 0;
            #pragma unroll
            for (int i = 0; i < NT; i++) {
                float v = sc[i] + tr[i * NT + tid];
                if (v > best) { best = v; bi = i; }   // first-max on ties
            }
            const int m = xs[b * SS + s] > 0;
            const float em = g_emis[((size_t)b * SS + s) * NT + tid];
            ns = m ? (best + em) : sc[tid];
            nb = m ? bi : tid;
        }
        __syncwarp();
        if (tid < NT) { sc[tid] = ns; bp[s * NT + tid] = (unsigned char)nb; }
        __syncwarp();
    }

    if (tid == 0) {
        float best = -1e30f; int bi = 0;
        for (int j = 0; j < NT; j++) {
            float v = sc[j] + end_t[j];
            if (v > best) { best = v; bi = j; }
        }
        if (write_scores) out[b] = best;
        if (write_tags) {
            int tag = bi;
            out[tag_off + b * SS + (SS - 1)] = (float)tag;
            for (int s = SS - 2; s >= 0; s--) {
                tag = bp[(s + 1) * NT + tag];
                out[tag_off + b * SS + s] = (float)tag;
            }
        }
    }
}

// ---------------- launch ----------------
extern "C" void kernel_launch(void* const* d_in, const int* in_sizes, int n_in,
                              void* d_out, int out_size)
{
    const int*   xs      = (const int*)  d_in[0];
    const float* emb     = (const float*)d_in[1];
    const float* W_ih_f  = (const float*)d_in[2];
    const float* W_hh_f  = (const float*)d_in[3];
    const float* b_f     = (const float*)d_in[4];
    const float* W_ih_r  = (const float*)d_in[5];
    const float* W_hh_r  = (const float*)d_in[6];
    const float* b_r     = (const float*)d_in[7];
    const float* fc_W    = (const float*)d_in[8];
    const float* fc_b    = (const float*)d_in[9];
    const float* trans   = (const float*)d_in[10];
    const float* start_t = (const float*)d_in[11];
    const float* end_t   = (const float*)d_in[12];
    float* out = (float*)d_out;

    cudaFuncSetAttribute(lstm_kernel, cudaFuncAttributeMaxDynamicSharedMemorySize, LSTM_SMEM);

    init_kernel<<<256, 256>>>();

    dim3 gA(M_TOT / 64, G4 / 64, 2);
    input_proj_kernel<<<gA, 256>>>(xs, emb, W_ih_f, b_f, W_ih_r, b_r);

    lstm_kernel<<<2 * NBLK, 256, LSTM_SMEM>>>(W_hh_f, W_hh_r);

    emis_kernel<<<M_TOT / 8, 256>>>(fc_W, fc_b);

    int ws = 0, wt = 0, toff = 0;
    if (out_size >= BB + BB * SS)      { ws = 1; wt = 1; toff = BB; }
    else if (out_size >= BB * SS)      { ws = 0; wt = 1; toff = 0; }
    else                               { ws = 1; wt = 0; toff = 0; }
    viterbi_kernel<<<BB, 32>>>(xs, trans, start_t, end_t, out, ws, wt, toff);
}

// round 15
// speedup vs baseline: 2.8970x; 2.8970x over previous
#include <cuda_runtime.h>
#include <math.h>

#define BB 128
#define SS 512
#define EE 256
#define HH 256
#define G4 1024
#define NT 20
#define M_TOT (BB*SS)          // 65536
#define NBLK 64                // blocks per direction in lstm kernel
#define DPB 4                  // hidden dims per block

typedef unsigned long long ull;

// -------- device scratch (static: no allocations allowed) --------
// g_xp layout: [dir][t][gate_row 1024][b 128]  (536 MB)
__device__ float g_xp[2 * SS * G4 * BB];
__device__ float g_hout[2 * M_TOT * HH];   // [dir][b*S+t][H]
__device__ float g_hcur[2 * 2 * HH * BB];  // [dir][parity][hd][b]
__device__ float g_emis[M_TOT * NT];       // [b*S+s][T]
__device__ unsigned g_bar_cnt[2];
__device__ unsigned g_bar_flag[2];

// smem floats: h 256*128 + w 256*16 + pg 2*16*128 + x 16*128 + c 4*128
#define LSTM_SMEM ((256*128 + 256*16 + 2*16*128 + 16*128 + 4*128) * 4)

// -------- packed f32x2 helpers (FFMA2 path, exact fp32) --------
__device__ __forceinline__ void upk2(ull v, float& lo, float& hi) {
    asm("mov.b64 {%0, %1}, %2;" : "=f"(lo), "=f"(hi) : "l"(v));
}
__device__ __forceinline__ ull dup2(float x) {
    ull r; asm("mov.b64 %0, {%1, %1};" : "=l"(r) : "f"(x)); return r;
}
__device__ __forceinline__ void fma2(ull& d, ull a, ull b) {
    asm("fma.rn.f32x2 %0, %1, %2, %0;" : "+l"(d) : "l"(a), "l"(b));
}
__device__ __forceinline__ void cp16(unsigned dst, const void* src) {
    asm volatile("cp.async.cg.shared.global [%0], [%1], 16;" :: "r"(dst), "l"(src));
}
#define CP_COMMIT() asm volatile("cp.async.commit_group;")

// ---------------- init: reset barriers + zero h state ----------------
__global__ void init_kernel() {
    int idx = blockIdx.x * blockDim.x + threadIdx.x;
    int stride = gridDim.x * blockDim.x;
    for (int i = idx; i < 2 * 2 * HH * BB; i += stride) g_hcur[i] = 0.f;
    if (idx == 0) {
        g_bar_cnt[0] = 0; g_bar_cnt[1] = 0;
        g_bar_flag[0] = 0; g_bar_flag[1] = 0;
    }
}

// ---------------- input projection: xp = emb[xs] @ W_ih^T + b ----------------
// Retiled: M = 64 batches at fixed t. Output written TRANSPOSED: g_xp[dir][t][n][b].
// 64x64 tile, K panels of 16, 256 threads, 4x4 per thread, register panel prefetch.
__global__ void input_proj_kernel(const int* __restrict__ xs,
                                  const float* __restrict__ emb,
                                  const float* __restrict__ W_f,
                                  const float* __restrict__ b_f,
                                  const float* __restrict__ W_r,
                                  const float* __restrict__ b_r)
{
    const int dir = blockIdx.z;
    const float* W    = dir ? W_r : W_f;
    const float* bias = dir ? b_r : b_f;
    const int t   = blockIdx.x >> 1;
    const int b0r = (blockIdx.x & 1) * 64;
    const int n0  = blockIdx.y * 64;

    __shared__ float As[16][68];
    __shared__ float Bs[16][68];

    const int tid = threadIdx.x;
    const int lr = tid >> 2;          // 0..63
    const int lk = (tid & 3) * 4;     // 0,4,8,12

    const int tok = xs[(b0r + lr) * SS + t];
    const float* arow = emb + (size_t)tok * EE;
    const float* brow = W + (size_t)(n0 + lr) * EE;

    const int ty = tid >> 4;          // 0..15 -> batches ty*4..+3
    const int tx = tid & 15;          // 0..15 -> cols tx*4..+3

    float acc[4][4];
    #pragma unroll
    for (int i = 0; i < 4; i++)
        #pragma unroll
        for (int j = 0; j < 4; j++) acc[i][j] = 0.f;

    float4 av = *(const float4*)(arow + lk);
    float4 bv = *(const float4*)(brow + lk);

    #pragma unroll 1
    for (int p = 0; p < 16; p++) {
        __syncthreads();
        As[lk+0][lr] = av.x; As[lk+1][lr] = av.y; As[lk+2][lr] = av.z; As[lk+3][lr] = av.w;
        Bs[lk+0][lr] = bv.x; Bs[lk+1][lr] = bv.y; Bs[lk+2][lr] = bv.z; Bs[lk+3][lr] = bv.w;
        __syncthreads();
        if (p < 15) {
            av = *(const float4*)(arow + (p + 1) * 16 + lk);
            bv = *(const float4*)(brow + (p + 1) * 16 + lk);
        }
        #pragma unroll
        for (int k = 0; k < 16; k++) {
            float4 a = *(const float4*)(&As[k][ty*4]);
            float4 b = *(const float4*)(&Bs[k][tx*4]);
            acc[0][0] += a.x*b.x; acc[0][1] += a.x*b.y; acc[0][2] += a.x*b.z; acc[0][3] += a.x*b.w;
            acc[1][0] += a.y*b.x; acc[1][1] += a.y*b.y; acc[1][2] += a.y*b.z; acc[1][3] += a.y*b.w;
            acc[2][0] += a.z*b.x; acc[2][1] += a.z*b.y; acc[2][2] += a.z*b.z; acc[2][3] += a.z*b.w;
            acc[3][0] += a.w*b.x; acc[3][1] += a.w*b.y; acc[3][2] += a.w*b.z; acc[3][3] += a.w*b.w;
        }
    }

    // transposed store: g_xp[((dir*SS+t)*G4 + n)*BB + b]
    const size_t obase = ((size_t)dir * SS + t) * G4;
    float4 bv4 = *(const float4*)(bias + n0 + tx * 4);
    const float bscal[4] = { bv4.x, bv4.y, bv4.z, bv4.w };
    #pragma unroll
    for (int j = 0; j < 4; j++) {
        const int n = n0 + tx * 4 + j;
        float4 o;
        o.x = acc[0][j] + bscal[j]; o.y = acc[1][j] + bscal[j];
        o.z = acc[2][j] + bscal[j]; o.w = acc[3][j] + bscal[j];
        *(float4*)(g_xp + (obase + n) * BB + b0r + ty * 4) = o;
    }
}

// ---------------- persistent bidirectional LSTM recurrence ----------------
// 128 blocks: [0,64) fwd, [64,128) rev. Block owns 4 hidden dims = 16 gate cols.
// 16 cells/thread (4b x 4c), k-split halves, FFMA2 with register-duplicated W.
__global__ void __launch_bounds__(256, 1) lstm_kernel(const float* __restrict__ W_f,
                                                      const float* __restrict__ W_r)
{
    extern __shared__ float sm[];
    float* h_s = sm;                       // [k=256][b=128]
    float* w_s = h_s + 256 * 128;          // [k=256][c=16]
    float* pg  = w_s + 256 * 16;           // [half=2][c=16][b=128]
    float* x_s = pg  + 2 * 16 * 128;       // [c=16][b=128]
    float* c_s = x_s + 16 * 128;           // [d=4][b=128]

    const int tid = threadIdx.x;
    const int dir = blockIdx.x >> 6;
    const int blk = blockIdx.x & 63;
    const int d0  = blk * DPB;
    const float* W = dir ? W_r : W_f;

    // load W slice transposed: w_s[k][c] = W[q*256+d0+dd][k], c = q*4+dd
    {
        const int c  = tid >> 4;               // 0..15
        const int q  = c >> 2, dd = c & 3;
        const int grow = q * 256 + d0 + dd;
        const int kc = (tid & 15) * 16;
        const float* wp = W + (size_t)grow * 256 + kc;
        #pragma unroll
        for (int kk = 0; kk < 16; kk++)
            w_s[(kc + kk) * 16 + c] = wp[kk];
    }
    for (int i = tid; i < DPB * BB; i += 256) c_s[i] = 0.f;
    __syncthreads();

    const int half = tid >> 7;           // k range half*128 .. +128
    const int wt   = tid & 127;
    const int bg   = wt >> 2;            // 0..31 -> batches bg*4..+3
    const int cq   = wt & 3;             // 0..3  -> cols cq*4..+3 (gate cq, dims 0..3)
    const int b0   = bg * 4;

    const float* xpT       = g_xp   + (size_t)dir * SS * G4 * BB;
    float*       hout_base = g_hout + (size_t)dir * M_TOT * HH;
    const unsigned h_addr = (unsigned)__cvta_generic_to_shared(h_s);
    const unsigned x_addr = (unsigned)__cvta_generic_to_shared(x_s);

    for (int ti = 0; ti < SS; ti++) {
        const int t = dir ? (SS - 1 - ti) : ti;
        const int par = ti & 1;
        const float* hr = g_hcur + (dir * 2 + par) * (HH * BB);
        float*       hw = g_hcur + (dir * 2 + (par ^ 1)) * (HH * BB);

        // --- staging: half0 copies h rows 0..127 + xp; half1 copies h rows 128..255
        if (half == 0) {
            const float4* src = (const float4*)hr;
            #pragma unroll
            for (int i = 0; i < 32; i++) {
                int idx = i * 128 + wt;            // 0..4095 (rows 0..127)
                cp16(h_addr + idx * 16, src + idx);
            }
            CP_COMMIT();
            const float* xt = xpT + (size_t)t * G4 * BB;
            #pragma unroll
            for (int i = 0; i < 4; i++) {
                int id = i * 128 + wt;             // 0..511 float4 units
                int c = id >> 5, bq = id & 31;
                int q = c >> 2, dd = c & 3;
                const float* s = xt + (size_t)(q * 256 + d0 + dd) * BB + bq * 4;
                cp16(x_addr + id * 16, s);
            }
            CP_COMMIT();
            asm volatile("cp.async.wait_group 1;");   // h rows 0..127 done
            asm volatile("bar.sync 1, 128;");
        } else {
            const float4* src = (const float4*)hr;
            #pragma unroll
            for (int i = 0; i < 32; i++) {
                int idx = 4096 + i * 128 + wt;     // rows 128..255
                cp16(h_addr + idx * 16, src + idx);
            }
            CP_COMMIT();
            asm volatile("cp.async.wait_group 0;");
            asm volatile("bar.sync 2, 128;");
        }

        // --- GEMM over this half's k range: 16 cells (4b x 4c), FFMA2 batch pairs
        ull a0[4], a1[4];   // a0[j] = (b0,b1) col j ; a1[j] = (b2,b3) col j
        #pragma unroll
        for (int j = 0; j < 4; j++) { a0[j] = 0ull; a1[j] = 0ull; }

        const float* hp = h_s + half * 128 * 128 + b0;
        const float* wp = w_s + half * 128 * 16 + cq * 4;
        #pragma unroll 8
        for (int k = 0; k < 128; k++) {
            ulonglong2 hv = *(const ulonglong2*)(hp + k * 128);
            float4 wv = *(const float4*)(wp + k * 16);
            ull w0 = dup2(wv.x), w1 = dup2(wv.y), w2 = dup2(wv.z), w3 = dup2(wv.w);
            fma2(a0[0], hv.x, w0); fma2(a1[0], hv.y, w0);
            fma2(a0[1], hv.x, w1); fma2(a1[1], hv.y, w1);
            fma2(a0[2], hv.x, w2); fma2(a1[2], hv.y, w2);
            fma2(a0[3], hv.x, w3); fma2(a1[3], hv.y, w3);
        }

        // write partials: pg[half][c][b]
        {
            float* pgh = pg + half * 2048;
            #pragma unroll
            for (int j = 0; j < 4; j++) {
                ulonglong2 s; s.x = a0[j]; s.y = a1[j];
                *(ulonglong2*)(pgh + (cq * 4 + j) * 128 + b0) = s;
            }
        }
        if (half == 0) asm volatile("cp.async.wait_group 0;");  // xp group done
        __syncthreads();

        // --- gate math: 512 (d,b) pairs, 2 per thread
        #pragma unroll
        for (int r = 0; r < 2; r++) {
            const int idx = tid + r * 256;
            const int d = idx >> 7, b = idx & 127;
            const float gi = pg[(0*4+d)*128+b] + pg[2048+(0*4+d)*128+b] + x_s[(0*4+d)*128+b];
            const float gf = pg[(1*4+d)*128+b] + pg[2048+(1*4+d)*128+b] + x_s[(1*4+d)*128+b];
            const float gg = pg[(2*4+d)*128+b] + pg[2048+(2*4+d)*128+b] + x_s[(2*4+d)*128+b];
            const float go = pg[(3*4+d)*128+b] + pg[2048+(3*4+d)*128+b] + x_s[(3*4+d)*128+b];
            const float cp = c_s[d * 128 + b];
            const float si = 1.f / (1.f + expf(-gi));
            const float sf = 1.f / (1.f + expf(-gf));
            const float so = 1.f / (1.f + expf(-go));
            const float cn = sf * cp + si * tanhf(gg);
            const float hv = so * tanhf(cn);
            c_s[d * 128 + b] = cn;
            __stcg(hw + (d0 + d) * BB + b, hv);
            hout_base[((size_t)b * SS + t) * HH + d0 + d] = hv;
        }

        // --- grid barrier for this direction
        __syncthreads();
        if (tid == 0) {
            __threadfence();
            const unsigned target = (unsigned)(NBLK * (ti + 1));
            const unsigned a = atomicAdd(&g_bar_cnt[dir], 1u);
            if (a == target - 1) {
                atomicExch(&g_bar_flag[dir], (unsigned)(ti + 1));
            } else {
                const unsigned* fp = &g_bar_flag[dir];
                unsigned f;
                do {
                    asm volatile("ld.global.cg.u32 %0, [%1];" : "=r"(f) : "l"(fp));
                    if (f >= (unsigned)(ti + 1)) break;
                    __nanosleep(32);
                } while (true);
            }
        }
        __syncthreads();
    }
}

// ---------------- emissions: concat(h_f,h_r) @ fc_W^T + fc_b ----------------
__global__ void emis_kernel(const float* __restrict__ fcW, const float* __restrict__ fcb)
{
    __shared__ float w_sh[NT * 2 * HH];   // 40 KB
    __shared__ float b_sh[NT];
    const int tid = threadIdx.x;
    for (int i = tid; i < NT * 2 * HH; i += 256) w_sh[i] = fcW[i];
    if (tid < NT) b_sh[tid] = fcb[tid];
    __syncthreads();

    const int warp = tid >> 5, lane = tid & 31;
    const int pos = blockIdx.x * 8 + warp;  // 0..65535
    const float* hf = g_hout + (size_t)pos * HH;
    const float* hr = g_hout + (size_t)M_TOT * HH + (size_t)pos * HH;

    ulonglong2 Fa = *(const ulonglong2*)(hf + lane * 8);
    ulonglong2 Fb = *(const ulonglong2*)(hf + lane * 8 + 4);
    ulonglong2 Ra = *(const ulonglong2*)(hr + lane * 8);
    ulonglong2 Rb = *(const ulonglong2*)(hr + lane * 8 + 4);

    for (int tg = 0; tg < NT; tg++) {
        const float* w = w_sh + tg * 2 * HH;
        ulonglong2 Wa = *(const ulonglong2*)(w + lane * 8);
        ulonglong2 Wb = *(const ulonglong2*)(w + lane * 8 + 4);
        ulonglong2 Va = *(const ulonglong2*)(w + HH + lane * 8);
        ulonglong2 Vb = *(const ulonglong2*)(w + HH + lane * 8 + 4);
        ull acc = 0ull;
        fma2(acc, Fa.x, Wa.x); fma2(acc, Fa.y, Wa.y);
        fma2(acc, Fb.x, Wb.x); fma2(acc, Fb.y, Wb.y);
        fma2(acc, Ra.x, Va.x); fma2(acc, Ra.y, Va.y);
        fma2(acc, Rb.x, Vb.x); fma2(acc, Rb.y, Vb.y);
        float lo, hi; upk2(acc, lo, hi);
        float s = lo + hi;
        #pragma unroll
        for (int off = 16; off; off >>= 1) s += __shfl_xor_sync(0xffffffffu, s, off);
        if (lane == 0) g_emis[(size_t)pos * NT + tg] = s + b_sh[tg];
    }
}

// ---------------- Viterbi: one block (1 warp) per batch item ----------------
__global__ void viterbi_kernel(const int* __restrict__ xs,
                               const float* __restrict__ trans,
                               const float* __restrict__ start_t,
                               const float* __restrict__ end_t,
                               float* __restrict__ out,
                               int write_scores, int write_tags, int tag_off)
{
    __shared__ float tr[NT * NT];
    __shared__ float sc[NT];
    __shared__ unsigned char bp[SS * NT];

    const int b = blockIdx.x, tid = threadIdx.x;
    for (int i = tid; i < NT * NT; i += 32) tr[i] = trans[i];
    if (tid < NT) sc[tid] = start_t[tid] + g_emis[(size_t)b * SS * NT + tid];
    __syncwarp();

    for (int s = 1; s < SS; s++) {
        float ns = 0.f; int nb = 0;
        if (tid < NT) {
            float best = -1e30f; int bi = 0;
            #pragma unroll
            for (int i = 0; i < NT; i++) {
                float v = sc[i] + tr[i * NT + tid];
                if (v > best) { best = v; bi = i; }   // first-max on ties
            }
            const int m = xs[b * SS + s] > 0;
            const float em = g_emis[((size_t)b * SS + s) * NT + tid];
            ns = m ? (best + em) : sc[tid];
            nb = m ? bi : tid;
        }
        __syncwarp();
        if (tid < NT) { sc[tid] = ns; bp[s * NT + tid] = (unsigned char)nb; }
        __syncwarp();
    }

    if (tid == 0) {
        float best = -1e30f; int bi = 0;
        for (int j = 0; j < NT; j++) {
            float v = sc[j] + end_t[j];
            if (v > best) { best = v; bi = j; }
        }
        if (write_scores) out[b] = best;
        if (write_tags) {
            int tag = bi;
            out[tag_off + b * SS + (SS - 1)] = (float)tag;
            for (int s = SS - 2; s >= 0; s--) {
                tag = bp[(s + 1) * NT + tag];
                out[tag_off + b * SS + s] = (float)tag;
            }
        }
    }
}

// ---------------- launch ----------------
extern "C" void kernel_launch(void* const* d_in, const int* in_sizes, int n_in,
                              void* d_out, int out_size)
{
    const int*   xs      = (const int*)  d_in[0];
    const float* emb     = (const float*)d_in[1];
    const float* W_ih_f  = (const float*)d_in[2];
    const float* W_hh_f  = (const float*)d_in[3];
    const float* b_f     = (const float*)d_in[4];
    const float* W_ih_r  = (const float*)d_in[5];
    const float* W_hh_r  = (const float*)d_in[6];
    const float* b_r     = (const float*)d_in[7];
    const float* fc_W    = (const float*)d_in[8];
    const float* fc_b    = (const float*)d_in[9];
    const float* trans   = (const float*)d_in[10];
    const float* start_t = (const float*)d_in[11];
    const float* end_t   = (const float*)d_in[12];
    float* out = (float*)d_out;

    cudaFuncSetAttribute(lstm_kernel, cudaFuncAttributeMaxDynamicSharedMemorySize, LSTM_SMEM);

    init_kernel<<<256, 256>>>();

    // grid: x = t*2 + batch-half, y = n-tile, z = dir
    dim3 gA(SS * 2, G4 / 64, 2);
    input_proj_kernel<<<gA, 256>>>(xs, emb, W_ih_f, b_f, W_ih_r, b_r);

    lstm_kernel<<<2 * NBLK, 256, LSTM_SMEM>>>(W_hh_f, W_hh_r);

    emis_kernel<<<M_TOT / 8, 256>>>(fc_W, fc_b);

    int ws = 0, wt = 0, toff = 0;
    if (out_size >= BB + BB * SS)      { ws = 1; wt = 1; toff = BB; }
    else if (out_size >= BB * SS)      { ws = 0; wt = 1; toff = 0; }
    else                               { ws = 1; wt = 0; toff = 0; }
    viterbi_kernel<<<BB, 32>>>(xs, trans, start_t, end_t, out, ws, wt, toff);
}